// round 16
// baseline (speedup 1.0000x reference)
#include <cuda_runtime.h>
#include <cuda.h>
#include <cuda_fp16.h>
#include <cstdint>
#include <math.h>

#define DD 4096
#define SS 128
#define NK 15
#define TT (SS*NK)   // 1920 evaluation points

// ---------------------------------------------------------------------------
// Scratch (static device arrays; no allocation allowed)
// ---------------------------------------------------------------------------
__device__ __align__(16) __half g_PhiA[(size_t)TT * DD];  // Phi   [np][d]
__device__ __align__(16) __half g_PhiT[(size_t)DD * TT];  // Phi^T [d][np]
__device__ __align__(16) __half g_WT [(size_t)DD * DD];   // W^T   [n][k]
__device__ __align__(16) __half g_GT [(size_t)DD * TT];   // G^T   [d][np]

__constant__ float c_nodes[NK] = {
    0.20778495500789848f, 0.4058451513773972f, 0.5860872354676911f,
    0.7415311855993945f,  0.8648644233597691f, 0.9491079123427585f,
    0.9914553711208126f, -0.9914553711208126f, -0.9491079123427585f,
   -0.8648644233597691f, -0.7415311855993945f, -0.5860872354676911f,
   -0.4058451513773972f, -0.20778495500789848f, 0.0f
};
__constant__ float c_wk[NK] = {
    0.20443294007529889f, 0.19035057806478542f, 0.1690047266392679f,
    0.14065325971552592f, 0.10479001032225019f, 0.06309209262997856f,
    0.022935322010529224f, 0.022935322010529224f, 0.06309209262997856f,
    0.10479001032225019f, 0.14065325971552592f, 0.1690047266392679f,
    0.19035057806478542f, 0.20443294007529889f, 0.20948214108472782f
};

__device__ __forceinline__ void node_params(int n, float* tval, float* hwk) {
    int s = n / NK;
    int k = n - s * NK;
    float a = (float)s       * (1.0f/128.0f);
    float b = (float)(s + 1) * (1.0f/128.0f);
    float h = 0.5f * (b - a);
    float c = 0.5f * (a + b);
    *tval = c + h * c_nodes[k];
    *hwk  = h * c_wk[k];
}

__device__ __forceinline__ uint32_t smem_u32(const void* p) {
    uint32_t a;
    asm("{ .reg .u64 t; cvta.to.shared.u64 t, %1; cvt.u32.u64 %0, t; }" : "=r"(a) : "l"(p));
    return a;
}

__device__ __forceinline__ void cp16(uint32_t saddr, const void* g) {
    asm volatile("cp.async.cg.shared.global [%0], [%1], 16;\n" :: "r"(saddr), "l"(g) : "memory");
}
__device__ __forceinline__ void cp_commit() { asm volatile("cp.async.commit_group;\n" ::: "memory"); }
template<int N>
__device__ __forceinline__ void cp_wait() { asm volatile("cp.async.wait_group %0;\n" :: "n"(N) : "memory"); }

__device__ __forceinline__ void ldsm4(uint32_t* r, uint32_t addr) {
    asm volatile("ldmatrix.sync.aligned.m8n8.x4.shared.b16 {%0,%1,%2,%3}, [%4];"
        : "=r"(r[0]), "=r"(r[1]), "=r"(r[2]), "=r"(r[3]) : "r"(addr));
}

__device__ __forceinline__ void mma_f16(float* c, const uint32_t* a, uint32_t b0, uint32_t b1) {
    asm volatile(
        "mma.sync.aligned.m16n8k16.row.col.f32.f16.f16.f32 "
        "{%0,%1,%2,%3}, {%4,%5,%6,%7}, {%8,%9}, {%0,%1,%2,%3};"
        : "+f"(c[0]), "+f"(c[1]), "+f"(c[2]), "+f"(c[3])
        : "r"(a[0]), "r"(a[1]), "r"(a[2]), "r"(a[3]), "r"(b0), "r"(b1));
}

// ---- TMA / mbarrier helpers (base sm_90 PTX, legal at compute_100) --------
__device__ __forceinline__ void mbar_init(uint32_t a, uint32_t cnt) {
    asm volatile("mbarrier.init.shared.b64 [%0], %1;" :: "r"(a), "r"(cnt) : "memory");
}
__device__ __forceinline__ void mbar_expect_tx(uint32_t a, uint32_t bytes) {
    asm volatile("mbarrier.arrive.expect_tx.shared.b64 _, [%0], %1;" :: "r"(a), "r"(bytes) : "memory");
}
__device__ __forceinline__ void tma2d(uint32_t dst, const CUtensorMap* tm, int x, int y, uint32_t mbar) {
    asm volatile(
        "cp.async.bulk.tensor.2d.shared::cta.global.tile.mbarrier::complete_tx::bytes "
        "[%0], [%1, {%2, %3}], [%4];"
        :: "r"(dst), "l"(tm), "r"(x), "r"(y), "r"(mbar) : "memory");
}
__device__ __forceinline__ void mbar_wait(uint32_t a, uint32_t parity) {
    uint32_t done;
    asm volatile(
        "{\n\t.reg .pred p;\n\t"
        "mbarrier.try_wait.parity.acquire.cta.shared::cta.b64 p, [%1], %2;\n\t"
        "selp.b32 %0, 1, 0, p;\n\t}"
        : "=r"(done) : "r"(a), "r"(parity) : "memory");
    if (!done) {
        asm volatile(
            "{\n\t.reg .pred P1;\n\t"
            "WL_%=:\n\t"
            "mbarrier.try_wait.parity.acquire.cta.shared::cta.b64 P1, [%0], %1, 0x989680;\n\t"
            "@P1 bra.uni WD_%=;\n\t"
            "bra.uni WL_%=;\n\t"
            "WD_%=:\n\t}"
            :: "r"(a), "r"(parity) : "memory");
    }
}

// ---------------------------------------------------------------------------
// Prep kernels
// ---------------------------------------------------------------------------
__global__ __launch_bounds__(256) void phi_both_kernel(const float* __restrict__ freqs) {
    __shared__ float tile[32][33];
    int nb = blockIdx.x;          // 60  (TT/32)
    int db = blockIdx.y;          // 128 (DD/32)
    int tx = threadIdx.x & 31, ty = threadIdx.x >> 5;
    int d = db * 32 + tx;
    float f = freqs[d];
    #pragma unroll
    for (int q = 0; q < 4; q++) {
        int n = nb * 32 + ty + q * 8;
        float tval, hwk; node_params(n, &tval, &hwk);
        float s = __sinf(tval * f);           // arg in [0,3]; abs err ~1e-6 << fp16 ulp
        g_PhiA[(size_t)n * DD + d] = __float2half_rn(s);
        tile[ty + q * 8][tx] = s;
    }
    __syncthreads();
    #pragma unroll
    for (int q = 0; q < 4; q++) {
        int dr = db * 32 + ty + q * 8;
        int n  = nb * 32 + tx;
        g_PhiT[(size_t)dr * TT + n] = __float2half_rn(tile[tx][ty + q * 8]);
    }
}

__global__ __launch_bounds__(256) void wt_kernel(const float* __restrict__ W) {
    __shared__ float t[32][33];
    int k0 = blockIdx.x * 32, n0 = blockIdx.y * 32;
    int tx = threadIdx.x & 31, ty = threadIdx.x >> 5;
    for (int i = ty; i < 32; i += 8)
        t[i][tx] = W[(size_t)(k0 + i) * DD + n0 + tx];
    __syncthreads();
    for (int i = ty; i < 32; i += 8)
        g_WT[(size_t)(n0 + i) * DD + k0 + tx] = __float2half_rn(t[tx][i]);
}

// ---------------------------------------------------------------------------
// HMMA GEMM: D(128x128, fp32) = A(128xK) * B(128xK)^T, fp16.
// MODE 1: A=Phi, B=WT -> epilogue writes GT.   MODE 2: A=PhiT, B=GT -> Out.
// 256 threads, 8 warps 4m x 2n, warp tile 32x64, 3-stage pipeline, 2 CTAs/SM.
// TMA=1: warp0-only full-wait + bar.sync publication (proven sync placement).
// TMA=0: cp.async fallback.
// ---------------------------------------------------------------------------
#define BK 64
#define NSTAGE 3
#define A_BYTES 16384
#define STAGE_BYTES 32768
#define SMEM_DYN (NSTAGE * STAGE_BYTES + 64 + 1024)

// 128B rows, 8 x 16B segs; phys seg = seg ^ (row&7)  (== CU_TENSOR_MAP_SWIZZLE_128B)
__device__ __forceinline__ uint32_t swz(int row, int seg) {
    return (uint32_t)(row * 128 + ((seg ^ (row & 7)) << 4));
}

__device__ __forceinline__ void load_chunk(
    const __half* __restrict__ A, const __half* __restrict__ B,
    int K, int m0, int n0, int k0, uint32_t stage, int tid)
{
    #pragma unroll
    for (int it = 0; it < 8; it++) {
        int u = tid + it * 256;
        uint32_t dst; const __half* src;
        if (u < 1024) {
            int row = u >> 3, seg = u & 7;
            dst = stage + swz(row, seg);
            src = A + (size_t)(m0 + row) * K + k0 + seg * 8;
        } else {
            int v = u - 1024;
            int row = v >> 3, seg = v & 7;
            dst = stage + A_BYTES + swz(row, seg);
            src = B + (size_t)(n0 + row) * K + k0 + seg * 8;
        }
        cp16(dst, src);
    }
    cp_commit();
}

template<int MODE, int TMA>
__global__ void __launch_bounds__(256, 2) gemm_kernel(
    const float* __restrict__ bvec, const float* __restrict__ afreqs,
    float* __restrict__ Out,
    const __grid_constant__ CUtensorMap tmA,
    const __grid_constant__ CUtensorMap tmB)
{
    extern __shared__ char smem[];
    const uint32_t raw = smem_u32(smem);
    const uint32_t sb = (raw + 1023u) & ~1023u;   // 1024-align for SW128
    const uint32_t mb = sb + NSTAGE * STAGE_BYTES;
    char* smem_al = smem + (sb - raw);
    const int tid  = threadIdx.x;
    const int wid  = tid >> 5;
    const int lane = tid & 31;
    const int warpm = wid & 3;          // 4 m-blocks of 32
    const int warpn = wid >> 2;         // 2 n-blocks of 64
    const int g  = lane >> 2;
    const int t4 = lane & 3;

    const int K   = (MODE == 1) ? DD : TT;
    const int nch = K / BK;             // 64 or 30
    const int m0  = blockIdx.y * 128;
    const int n0  = blockIdx.x * 128;

    const __half* A = (MODE == 1) ? g_PhiA : g_PhiT;
    const __half* B = (MODE == 1) ? g_WT   : g_GT;

    float acc[2][8][4];
    #pragma unroll
    for (int i = 0; i < 2; i++)
        #pragma unroll
        for (int j = 0; j < 8; j++)
            #pragma unroll
            for (int r = 0; r < 4; r++) acc[i][j][r] = 0.0f;

    // prologue
    if (TMA) {
        if (tid == 0) {
            mbar_init(mb + 0, 1);
            mbar_init(mb + 8, 1);
            mbar_init(mb + 16, 1);
        }
        __syncthreads();
        if (tid == 0) {
            #pragma unroll
            for (int c = 0; c < 2; c++) {
                uint32_t bar = mb + c * 8;
                mbar_expect_tx(bar, STAGE_BYTES);
                tma2d(sb + c * STAGE_BYTES,           &tmA, c * BK, m0, bar);
                tma2d(sb + c * STAGE_BYTES + A_BYTES, &tmB, c * BK, n0, bar);
            }
        }
    } else {
        load_chunk(A, B, K, m0, n0, 0,  sb,               tid);
        load_chunk(A, B, K, m0, n0, BK, sb + STAGE_BYTES, tid);
    }

    // ldmatrix lane addressing
    const int a_row_l = warpm * 32 + (lane & 15);
    const int a_hiseg = lane >> 4;
    const int b_row_l = warpn * 64 + ((lane >> 4) << 3) + (lane & 7);
    const int b_hiseg = (lane >> 3) & 1;

    int stage = 0, phase = 0;
    for (int i = 0; i < nch; i++) {
        if (TMA) {
            // warp 0 acquires the full barrier; bar.sync publishes to all warps
            if (wid == 0) mbar_wait(mb + stage * 8, phase);
            __syncthreads();
            if (tid == 0 && i + 2 < nch) {
                int s2 = stage + 2; if (s2 >= NSTAGE) s2 -= NSTAGE;
                uint32_t bar = mb + s2 * 8;
                mbar_expect_tx(bar, STAGE_BYTES);
                tma2d(sb + s2 * STAGE_BYTES,           &tmA, (i + 2) * BK, m0, bar);
                tma2d(sb + s2 * STAGE_BYTES + A_BYTES, &tmB, (i + 2) * BK, n0, bar);
            }
        } else {
            if (i < nch - 1) cp_wait<1>(); else cp_wait<0>();
            __syncthreads();
            if (i + 2 < nch) {
                int s2 = stage + 2; if (s2 >= NSTAGE) s2 -= NSTAGE;
                load_chunk(A, B, K, m0, n0, (i + 2) * BK, sb + s2 * STAGE_BYTES, tid);
            }
        }

        const uint32_t st = sb + stage * STAGE_BYTES;
        #pragma unroll
        for (int j = 0; j < 4; j++) {
            uint32_t ah[2][4];
            #pragma unroll
            for (int fm = 0; fm < 2; fm++)
                ldsm4(ah[fm], st + swz(a_row_l + fm * 16, j * 2 + a_hiseg));
            #pragma unroll
            for (int fn = 0; fn < 4; fn++) {
                uint32_t b[4];
                ldsm4(b, st + A_BYTES + swz(b_row_l + fn * 16, j * 2 + b_hiseg));
                #pragma unroll
                for (int fm = 0; fm < 2; fm++)
                    #pragma unroll
                    for (int h = 0; h < 2; h++)
                        mma_f16(acc[fm][fn * 2 + h], ah[fm], b[h*2], b[h*2+1]);
            }
        }
        if (++stage == NSTAGE) { stage = 0; phase ^= 1; }
    }

    // -------------------- epilogue --------------------
    if (MODE == 2) {
        #pragma unroll
        for (int fm = 0; fm < 2; fm++) {
            #pragma unroll
            for (int h8 = 0; h8 < 2; h8++) {
                int d1 = m0 + warpm * 32 + fm * 16 + g + h8 * 8;
                float* orow = Out + (size_t)d1 * DD + n0 + warpn * 64 + t4 * 2;
                #pragma unroll
                for (int fn = 0; fn < 8; fn++) {
                    float2 v;
                    v.x = acc[fm][fn][h8 * 2 + 0];
                    v.y = acc[fm][fn][h8 * 2 + 1];
                    *(float2*)(orow + fn * 8) = v;
                }
            }
        }
        return;
    }

    // MODE 1: g = hwk * cos(t*afreq) * sech2(z+b), fast-math; write GT (fp16)
    // staging: S[128 np][136 d] fp16, row stride 272B
    float tv[4], hw[4];
    #pragma unroll
    for (int fm = 0; fm < 2; fm++)
        #pragma unroll
        for (int h8 = 0; h8 < 2; h8++) {
            int np = m0 + warpm * 32 + fm * 16 + g + h8 * 8;
            node_params(np, &tv[fm * 2 + h8], &hw[fm * 2 + h8]);
        }

    __syncthreads();
    #pragma unroll
    for (int fm = 0; fm < 2; fm++) {
        #pragma unroll
        for (int h8 = 0; h8 < 2; h8++) {
            int np_loc = warpm * 32 + fm * 16 + g + h8 * 8;
            float tval = tv[fm * 2 + h8], hwk = hw[fm * 2 + h8];
            #pragma unroll
            for (int fn = 0; fn < 8; fn++) {
                int d_loc = warpn * 64 + fn * 8 + t4 * 2;
                int d = n0 + d_loc;
                float z0 = acc[fm][fn][h8 * 2 + 0] + bvec[d];
                float z1 = acc[fm][fn][h8 * 2 + 1] + bvec[d + 1];
                float u0 = __expf(2.0f * z0);
                float u1 = __expf(2.0f * z1);
                float s0 = __fdividef(4.0f * u0, (1.0f + u0) * (1.0f + u0));
                float s1 = __fdividef(4.0f * u1, (1.0f + u1) * (1.0f + u1));
                float g0 = hwk * __cosf(tval * afreqs[d])     * s0;
                float g1 = hwk * __cosf(tval * afreqs[d + 1]) * s1;
                __half2 v;
                v.x = __float2half_rn(g0);
                v.y = __float2half_rn(g1);
                *(__half2*)(smem_al + np_loc * 272 + d_loc * 2) = v;
            }
        }
    }
    __syncthreads();
    {
        int d = tid >> 1;
        int seg2 = tid & 1;
        __half* grow = g_GT + (size_t)(n0 + d) * TT + m0 + seg2 * 64;
        #pragma unroll
        for (int c = 0; c < 8; c++) {
            __half vals[8];
            #pragma unroll
            for (int q = 0; q < 8; q++)
                vals[q] = *(__half*)(smem_al + (seg2 * 64 + c * 8 + q) * 272 + d * 2);
            *(uint4*)(grow + c * 8) = *(uint4*)vals;
        }
    }
}

// ---------------------------------------------------------------------------
typedef CUresult (*EncodeFn)(CUtensorMap*, CUtensorMapDataType, cuuint32_t, void*,
                             const cuuint64_t*, const cuuint64_t*, const cuuint32_t*,
                             const cuuint32_t*, CUtensorMapInterleave, CUtensorMapSwizzle,
                             CUtensorMapL2promotion, CUtensorMapFloatOOBfill);

static bool make_map(EncodeFn enc, CUtensorMap* m, void* base, uint64_t d0, uint64_t d1) {
    cuuint64_t dims[2]    = {d0, d1};
    cuuint64_t strides[1] = {d0 * 2};          // bytes
    cuuint32_t box[2]     = {64, 128};
    cuuint32_t estr[2]    = {1, 1};
    return enc(m, CU_TENSOR_MAP_DATA_TYPE_FLOAT16, 2, base, dims, strides, box, estr,
               CU_TENSOR_MAP_INTERLEAVE_NONE, CU_TENSOR_MAP_SWIZZLE_128B,
               CU_TENSOR_MAP_L2_PROMOTION_L2_128B,
               CU_TENSOR_MAP_FLOAT_OOB_FILL_NONE) == (CUresult)0;
}

extern "C" void kernel_launch(void* const* d_in, const int* in_sizes, int n_in,
                              void* d_out, int out_size) {
    const float* W      = (const float*)d_in[0];
    const float* b      = (const float*)d_in[1];
    const float* freqs  = (const float*)d_in[2];
    const float* afreqs = (const float*)d_in[3];
    float* Out = (float*)d_out;

    cudaFuncSetAttribute(gemm_kernel<1,1>, cudaFuncAttributeMaxDynamicSharedMemorySize, SMEM_DYN);
    cudaFuncSetAttribute(gemm_kernel<2,1>, cudaFuncAttributeMaxDynamicSharedMemorySize, SMEM_DYN);
    cudaFuncSetAttribute(gemm_kernel<1,0>, cudaFuncAttributeMaxDynamicSharedMemorySize, SMEM_DYN);
    cudaFuncSetAttribute(gemm_kernel<2,0>, cudaFuncAttributeMaxDynamicSharedMemorySize, SMEM_DYN);

    // Resolve cuTensorMapEncodeTiled through cudart (no -lcuda needed)
    CUtensorMap tA1{}, tB1{}, tA2{}, tB2{};
    bool use_tma = false;
    {
        EncodeFn enc = nullptr;
        cudaDriverEntryPointQueryResult qr = cudaDriverEntryPointSymbolNotFound;
        if (cudaGetDriverEntryPointByVersion("cuTensorMapEncodeTiled", (void**)&enc,
                                             12000, cudaEnableDefault, &qr) == cudaSuccess &&
            qr == cudaDriverEntryPointSuccess && enc) {
            void *pA, *pT, *pW, *pG;
            if (cudaGetSymbolAddress(&pA, g_PhiA) == cudaSuccess &&
                cudaGetSymbolAddress(&pT, g_PhiT) == cudaSuccess &&
                cudaGetSymbolAddress(&pW, g_WT)  == cudaSuccess &&
                cudaGetSymbolAddress(&pG, g_GT)  == cudaSuccess) {
                use_tma = make_map(enc, &tA1, pA, DD, TT)    // Phi   [1920][4096]
                       && make_map(enc, &tB1, pW, DD, DD)    // WT    [4096][4096]
                       && make_map(enc, &tA2, pT, TT, DD)    // PhiT  [4096][1920]
                       && make_map(enc, &tB2, pG, TT, DD);   // GT    [4096][1920]
            }
        }
    }

    phi_both_kernel<<<dim3(TT/32, DD/32), 256>>>(freqs);
    wt_kernel<<<dim3(DD/32, DD/32), 256>>>(W);

    if (use_tma) {
        gemm_kernel<1,1><<<dim3(32, 15), 256, SMEM_DYN>>>(b, afreqs, nullptr, tA1, tB1);
        gemm_kernel<2,1><<<dim3(32, 32), 256, SMEM_DYN>>>(nullptr, nullptr, Out, tA2, tB2);
    } else {
        gemm_kernel<1,0><<<dim3(32, 15), 256, SMEM_DYN>>>(b, afreqs, nullptr, tA1, tB1);
        gemm_kernel<2,0><<<dim3(32, 32), 256, SMEM_DYN>>>(nullptr, nullptr, Out, tA2, tB2);
    }
}

// round 17
// speedup vs baseline: 1.0037x; 1.0037x over previous
#include <cuda_runtime.h>
#include <cuda.h>
#include <cuda_fp16.h>
#include <cstdint>
#include <math.h>

#define DD 4096
#define SS 128
#define NK 15
#define TT (SS*NK)   // 1920 evaluation points

// ---------------------------------------------------------------------------
// Scratch (static device arrays; no allocation allowed)
// ---------------------------------------------------------------------------
__device__ __align__(16) __half g_PhiA[(size_t)TT * DD];  // Phi   [np][d]
__device__ __align__(16) __half g_PhiT[(size_t)DD * TT];  // Phi^T [d][np]
__device__ __align__(16) __half g_WT [(size_t)DD * DD];   // W^T   [n][k]
__device__ __align__(16) __half g_GT [(size_t)DD * TT];   // G^T   [d][np]

__constant__ float c_nodes[NK] = {
    0.20778495500789848f, 0.4058451513773972f, 0.5860872354676911f,
    0.7415311855993945f,  0.8648644233597691f, 0.9491079123427585f,
    0.9914553711208126f, -0.9914553711208126f, -0.9491079123427585f,
   -0.8648644233597691f, -0.7415311855993945f, -0.5860872354676911f,
   -0.4058451513773972f, -0.20778495500789848f, 0.0f
};
__constant__ float c_wk[NK] = {
    0.20443294007529889f, 0.19035057806478542f, 0.1690047266392679f,
    0.14065325971552592f, 0.10479001032225019f, 0.06309209262997856f,
    0.022935322010529224f, 0.022935322010529224f, 0.06309209262997856f,
    0.10479001032225019f, 0.14065325971552592f, 0.1690047266392679f,
    0.19035057806478542f, 0.20443294007529889f, 0.20948214108472782f
};

__device__ __forceinline__ void node_params(int n, float* tval, float* hwk) {
    int s = n / NK;
    int k = n - s * NK;
    float a = (float)s       * (1.0f/128.0f);
    float b = (float)(s + 1) * (1.0f/128.0f);
    float h = 0.5f * (b - a);
    float c = 0.5f * (a + b);
    *tval = c + h * c_nodes[k];
    *hwk  = h * c_wk[k];
}

__device__ __forceinline__ uint32_t smem_u32(const void* p) {
    uint32_t a;
    asm("{ .reg .u64 t; cvta.to.shared.u64 t, %1; cvt.u32.u64 %0, t; }" : "=r"(a) : "l"(p));
    return a;
}

__device__ __forceinline__ void cp16(uint32_t saddr, const void* g) {
    asm volatile("cp.async.cg.shared.global [%0], [%1], 16;\n" :: "r"(saddr), "l"(g) : "memory");
}
__device__ __forceinline__ void cp_commit() { asm volatile("cp.async.commit_group;\n" ::: "memory"); }
template<int N>
__device__ __forceinline__ void cp_wait() { asm volatile("cp.async.wait_group %0;\n" :: "n"(N) : "memory"); }

__device__ __forceinline__ void ldsm4(uint32_t* r, uint32_t addr) {
    asm volatile("ldmatrix.sync.aligned.m8n8.x4.shared.b16 {%0,%1,%2,%3}, [%4];"
        : "=r"(r[0]), "=r"(r[1]), "=r"(r[2]), "=r"(r[3]) : "r"(addr));
}

__device__ __forceinline__ void mma_f16(float* c, const uint32_t* a, uint32_t b0, uint32_t b1) {
    asm volatile(
        "mma.sync.aligned.m16n8k16.row.col.f32.f16.f16.f32 "
        "{%0,%1,%2,%3}, {%4,%5,%6,%7}, {%8,%9}, {%0,%1,%2,%3};"
        : "+f"(c[0]), "+f"(c[1]), "+f"(c[2]), "+f"(c[3])
        : "r"(a[0]), "r"(a[1]), "r"(a[2]), "r"(a[3]), "r"(b0), "r"(b1));
}

// ---- TMA / mbarrier helpers (base sm_90 PTX, legal at compute_100) --------
__device__ __forceinline__ void mbar_init(uint32_t a, uint32_t cnt) {
    asm volatile("mbarrier.init.shared.b64 [%0], %1;" :: "r"(a), "r"(cnt) : "memory");
}
__device__ __forceinline__ void mbar_expect_tx(uint32_t a, uint32_t bytes) {
    asm volatile("mbarrier.arrive.expect_tx.shared.b64 _, [%0], %1;" :: "r"(a), "r"(bytes) : "memory");
}
__device__ __forceinline__ void tma2d(uint32_t dst, const CUtensorMap* tm, int x, int y, uint32_t mbar) {
    asm volatile(
        "cp.async.bulk.tensor.2d.shared::cta.global.tile.mbarrier::complete_tx::bytes "
        "[%0], [%1, {%2, %3}], [%4];"
        :: "r"(dst), "l"(tm), "r"(x), "r"(y), "r"(mbar) : "memory");
}
__device__ __forceinline__ void mbar_wait(uint32_t a, uint32_t parity) {
    uint32_t done;
    asm volatile(
        "{\n\t.reg .pred p;\n\t"
        "mbarrier.try_wait.parity.acquire.cta.shared::cta.b64 p, [%1], %2;\n\t"
        "selp.b32 %0, 1, 0, p;\n\t}"
        : "=r"(done) : "r"(a), "r"(parity) : "memory");
    if (!done) {
        asm volatile(
            "{\n\t.reg .pred P1;\n\t"
            "WL_%=:\n\t"
            "mbarrier.try_wait.parity.acquire.cta.shared::cta.b64 P1, [%0], %1, 0x989680;\n\t"
            "@P1 bra.uni WD_%=;\n\t"
            "bra.uni WL_%=;\n\t"
            "WD_%=:\n\t}"
            :: "r"(a), "r"(parity) : "memory");
    }
}

// ---------------------------------------------------------------------------
// Merged prep kernel: blocks [0, PHI_BLOCKS) compute Phi/PhiT; the rest WT.
// phi part is issue-bound (MUFU/ALU), wt part is HBM-bound -> they overlap.
// ---------------------------------------------------------------------------
#define PHI_BLOCKS ((TT/32) * (DD/32))     // 7680
#define WT_BLOCKS  ((DD/32) * (DD/32))     // 16384

__global__ __launch_bounds__(256) void prep_kernel(
    const float* __restrict__ freqs, const float* __restrict__ W)
{
    __shared__ float tile[32][33];
    int tx = threadIdx.x & 31, ty = threadIdx.x >> 5;
    int bid = blockIdx.x;

    if (bid < PHI_BLOCKS) {
        int nb = bid % (TT/32);       // 60
        int db = bid / (TT/32);       // 128
        int d = db * 32 + tx;
        float f = freqs[d];
        #pragma unroll
        for (int q = 0; q < 4; q++) {
            int n = nb * 32 + ty + q * 8;
            float tval, hwk; node_params(n, &tval, &hwk);
            float s = __sinf(tval * f);   // arg in [0,3]; abs err ~1e-6 << fp16 ulp
            g_PhiA[(size_t)n * DD + d] = __float2half_rn(s);
            tile[ty + q * 8][tx] = s;
        }
        __syncthreads();
        #pragma unroll
        for (int q = 0; q < 4; q++) {
            int dr = db * 32 + ty + q * 8;
            int n  = nb * 32 + tx;
            g_PhiT[(size_t)dr * TT + n] = __float2half_rn(tile[tx][ty + q * 8]);
        }
    } else {
        int u = bid - PHI_BLOCKS;
        int k0 = (u & 127) * 32;
        int n0 = (u >> 7) * 32;
        for (int i = ty; i < 32; i += 8)
            tile[i][tx] = W[(size_t)(k0 + i) * DD + n0 + tx];
        __syncthreads();
        for (int i = ty; i < 32; i += 8)
            g_WT[(size_t)(n0 + i) * DD + k0 + tx] = __float2half_rn(tile[tx][i]);
    }
}

// ---------------------------------------------------------------------------
// HMMA GEMM: D(128x128, fp32) = A(128xK) * B(128xK)^T, fp16.
// MODE 1: A=Phi, B=WT -> epilogue writes GT.   MODE 2: A=PhiT, B=GT -> Out.
// 256 threads, 8 warps 4m x 2n, warp tile 32x64, 3-stage pipeline, 2 CTAs/SM.
// TMA=1: loads via cp.async.bulk.tensor (round-15 proven structure).
// TMA=0: cp.async fallback.
// ---------------------------------------------------------------------------
#define BK 64
#define NSTAGE 3
#define A_BYTES 16384
#define STAGE_BYTES 32768
#define SMEM_DYN (NSTAGE * STAGE_BYTES + 64 + 1024)

// 128B rows, 8 x 16B segs; phys seg = seg ^ (row&7)  (== CU_TENSOR_MAP_SWIZZLE_128B)
__device__ __forceinline__ uint32_t swz(int row, int seg) {
    return (uint32_t)(row * 128 + ((seg ^ (row & 7)) << 4));
}

__device__ __forceinline__ void load_chunk(
    const __half* __restrict__ A, const __half* __restrict__ B,
    int K, int m0, int n0, int k0, uint32_t stage, int tid)
{
    #pragma unroll
    for (int it = 0; it < 8; it++) {
        int u = tid + it * 256;
        uint32_t dst; const __half* src;
        if (u < 1024) {
            int row = u >> 3, seg = u & 7;
            dst = stage + swz(row, seg);
            src = A + (size_t)(m0 + row) * K + k0 + seg * 8;
        } else {
            int v = u - 1024;
            int row = v >> 3, seg = v & 7;
            dst = stage + A_BYTES + swz(row, seg);
            src = B + (size_t)(n0 + row) * K + k0 + seg * 8;
        }
        cp16(dst, src);
    }
    cp_commit();
}

template<int MODE, int TMA>
__global__ void __launch_bounds__(256, 2) gemm_kernel(
    const float* __restrict__ bvec, const float* __restrict__ afreqs,
    float* __restrict__ Out,
    const __grid_constant__ CUtensorMap tmA,
    const __grid_constant__ CUtensorMap tmB)
{
    extern __shared__ char smem[];
    const uint32_t raw = smem_u32(smem);
    const uint32_t sb = (raw + 1023u) & ~1023u;   // 1024-align for SW128
    const uint32_t mb = sb + NSTAGE * STAGE_BYTES;
    char* smem_al = smem + (sb - raw);
    const int tid  = threadIdx.x;
    const int wid  = tid >> 5;
    const int lane = tid & 31;
    const int warpm = wid & 3;          // 4 m-blocks of 32
    const int warpn = wid >> 2;         // 2 n-blocks of 64
    const int g  = lane >> 2;
    const int t4 = lane & 3;

    const int K   = (MODE == 1) ? DD : TT;
    const int nch = K / BK;             // 64 or 30
    const int m0  = blockIdx.y * 128;
    const int n0  = blockIdx.x * 128;

    const __half* A = (MODE == 1) ? g_PhiA : g_PhiT;
    const __half* B = (MODE == 1) ? g_WT   : g_GT;

    float acc[2][8][4];
    #pragma unroll
    for (int i = 0; i < 2; i++)
        #pragma unroll
        for (int j = 0; j < 8; j++)
            #pragma unroll
            for (int r = 0; r < 4; r++) acc[i][j][r] = 0.0f;

    // prologue
    if (TMA) {
        if (tid == 0) {
            mbar_init(mb + 0, 1);
            mbar_init(mb + 8, 1);
            mbar_init(mb + 16, 1);
        }
        __syncthreads();
        if (tid == 0) {
            #pragma unroll
            for (int c = 0; c < 2; c++) {
                uint32_t bar = mb + c * 8;
                mbar_expect_tx(bar, STAGE_BYTES);
                tma2d(sb + c * STAGE_BYTES,           &tmA, c * BK, m0, bar);
                tma2d(sb + c * STAGE_BYTES + A_BYTES, &tmB, c * BK, n0, bar);
            }
        }
    } else {
        load_chunk(A, B, K, m0, n0, 0,  sb,               tid);
        load_chunk(A, B, K, m0, n0, BK, sb + STAGE_BYTES, tid);
    }

    // ldmatrix lane addressing
    const int a_row_l = warpm * 32 + (lane & 15);
    const int a_hiseg = lane >> 4;
    const int b_row_l = warpn * 64 + ((lane >> 4) << 3) + (lane & 7);
    const int b_hiseg = (lane >> 3) & 1;

    int stage = 0, phase = 0;
    for (int i = 0; i < nch; i++) {
        if (TMA) {
            mbar_wait(mb + stage * 8, phase);
            __syncthreads();
            if (tid == 0 && i + 2 < nch) {
                int s2 = stage + 2; if (s2 >= NSTAGE) s2 -= NSTAGE;
                uint32_t bar = mb + s2 * 8;
                mbar_expect_tx(bar, STAGE_BYTES);
                tma2d(sb + s2 * STAGE_BYTES,           &tmA, (i + 2) * BK, m0, bar);
                tma2d(sb + s2 * STAGE_BYTES + A_BYTES, &tmB, (i + 2) * BK, n0, bar);
            }
        } else {
            if (i < nch - 1) cp_wait<1>(); else cp_wait<0>();
            __syncthreads();
            if (i + 2 < nch) {
                int s2 = stage + 2; if (s2 >= NSTAGE) s2 -= NSTAGE;
                load_chunk(A, B, K, m0, n0, (i + 2) * BK, sb + s2 * STAGE_BYTES, tid);
            }
        }

        const uint32_t st = sb + stage * STAGE_BYTES;
        #pragma unroll
        for (int j = 0; j < 4; j++) {
            uint32_t ah[2][4];
            #pragma unroll
            for (int fm = 0; fm < 2; fm++)
                ldsm4(ah[fm], st + swz(a_row_l + fm * 16, j * 2 + a_hiseg));
            #pragma unroll
            for (int fn = 0; fn < 4; fn++) {
                uint32_t b[4];
                ldsm4(b, st + A_BYTES + swz(b_row_l + fn * 16, j * 2 + b_hiseg));
                #pragma unroll
                for (int fm = 0; fm < 2; fm++)
                    #pragma unroll
                    for (int h = 0; h < 2; h++)
                        mma_f16(acc[fm][fn * 2 + h], ah[fm], b[h*2], b[h*2+1]);
            }
        }
        if (++stage == NSTAGE) { stage = 0; phase ^= 1; }
    }

    // -------------------- epilogue --------------------
    if (MODE == 2) {
        #pragma unroll
        for (int fm = 0; fm < 2; fm++) {
            #pragma unroll
            for (int h8 = 0; h8 < 2; h8++) {
                int d1 = m0 + warpm * 32 + fm * 16 + g + h8 * 8;
                float* orow = Out + (size_t)d1 * DD + n0 + warpn * 64 + t4 * 2;
                #pragma unroll
                for (int fn = 0; fn < 8; fn++) {
                    float2 v;
                    v.x = acc[fm][fn][h8 * 2 + 0];
                    v.y = acc[fm][fn][h8 * 2 + 1];
                    *(float2*)(orow + fn * 8) = v;
                }
            }
        }
        return;
    }

    // MODE 1: g = hwk * cos(t*afreq) * sech2(z+b), fast-math; write GT (fp16)
    // staging: S[128 np][136 d] fp16, row stride 272B
    float tv[4], hw[4];
    #pragma unroll
    for (int fm = 0; fm < 2; fm++)
        #pragma unroll
        for (int h8 = 0; h8 < 2; h8++) {
            int np = m0 + warpm * 32 + fm * 16 + g + h8 * 8;
            node_params(np, &tv[fm * 2 + h8], &hw[fm * 2 + h8]);
        }

    __syncthreads();
    #pragma unroll
    for (int fm = 0; fm < 2; fm++) {
        #pragma unroll
        for (int h8 = 0; h8 < 2; h8++) {
            int np_loc = warpm * 32 + fm * 16 + g + h8 * 8;
            float tval = tv[fm * 2 + h8], hwk = hw[fm * 2 + h8];
            #pragma unroll
            for (int fn = 0; fn < 8; fn++) {
                int d_loc = warpn * 64 + fn * 8 + t4 * 2;
                int d = n0 + d_loc;
                float z0 = acc[fm][fn][h8 * 2 + 0] + bvec[d];
                float z1 = acc[fm][fn][h8 * 2 + 1] + bvec[d + 1];
                float u0 = __expf(2.0f * z0);
                float u1 = __expf(2.0f * z1);
                float s0 = __fdividef(4.0f * u0, (1.0f + u0) * (1.0f + u0));
                float s1 = __fdividef(4.0f * u1, (1.0f + u1) * (1.0f + u1));
                float g0 = hwk * __cosf(tval * afreqs[d])     * s0;
                float g1 = hwk * __cosf(tval * afreqs[d + 1]) * s1;
                __half2 v;
                v.x = __float2half_rn(g0);
                v.y = __float2half_rn(g1);
                *(__half2*)(smem_al + np_loc * 272 + d_loc * 2) = v;
            }
        }
    }
    __syncthreads();
    {
        int d = tid >> 1;
        int seg2 = tid & 1;
        __half* grow = g_GT + (size_t)(n0 + d) * TT + m0 + seg2 * 64;
        #pragma unroll
        for (int c = 0; c < 8; c++) {
            __half vals[8];
            #pragma unroll
            for (int q = 0; q < 8; q++)
                vals[q] = *(__half*)(smem_al + (seg2 * 64 + c * 8 + q) * 272 + d * 2);
            *(uint4*)(grow + c * 8) = *(uint4*)vals;
        }
    }
}

// ---------------------------------------------------------------------------
typedef CUresult (*EncodeFn)(CUtensorMap*, CUtensorMapDataType, cuuint32_t, void*,
                             const cuuint64_t*, const cuuint64_t*, const cuuint32_t*,
                             const cuuint32_t*, CUtensorMapInterleave, CUtensorMapSwizzle,
                             CUtensorMapL2promotion, CUtensorMapFloatOOBfill);

static bool make_map(EncodeFn enc, CUtensorMap* m, void* base, uint64_t d0, uint64_t d1) {
    cuuint64_t dims[2]    = {d0, d1};
    cuuint64_t strides[1] = {d0 * 2};          // bytes
    cuuint32_t box[2]     = {64, 128};
    cuuint32_t estr[2]    = {1, 1};
    return enc(m, CU_TENSOR_MAP_DATA_TYPE_FLOAT16, 2, base, dims, strides, box, estr,
               CU_TENSOR_MAP_INTERLEAVE_NONE, CU_TENSOR_MAP_SWIZZLE_128B,
               CU_TENSOR_MAP_L2_PROMOTION_L2_128B,
               CU_TENSOR_MAP_FLOAT_OOB_FILL_NONE) == (CUresult)0;
}

extern "C" void kernel_launch(void* const* d_in, const int* in_sizes, int n_in,
                              void* d_out, int out_size) {
    const float* W      = (const float*)d_in[0];
    const float* b      = (const float*)d_in[1];
    const float* freqs  = (const float*)d_in[2];
    const float* afreqs = (const float*)d_in[3];
    float* Out = (float*)d_out;

    cudaFuncSetAttribute(gemm_kernel<1,1>, cudaFuncAttributeMaxDynamicSharedMemorySize, SMEM_DYN);
    cudaFuncSetAttribute(gemm_kernel<2,1>, cudaFuncAttributeMaxDynamicSharedMemorySize, SMEM_DYN);
    cudaFuncSetAttribute(gemm_kernel<1,0>, cudaFuncAttributeMaxDynamicSharedMemorySize, SMEM_DYN);
    cudaFuncSetAttribute(gemm_kernel<2,0>, cudaFuncAttributeMaxDynamicSharedMemorySize, SMEM_DYN);

    // Resolve cuTensorMapEncodeTiled through cudart (no -lcuda needed)
    CUtensorMap tA1{}, tB1{}, tA2{}, tB2{};
    bool use_tma = false;
    {
        EncodeFn enc = nullptr;
        cudaDriverEntryPointQueryResult qr = cudaDriverEntryPointSymbolNotFound;
        if (cudaGetDriverEntryPointByVersion("cuTensorMapEncodeTiled", (void**)&enc,
                                             12000, cudaEnableDefault, &qr) == cudaSuccess &&
            qr == cudaDriverEntryPointSuccess && enc) {
            void *pA, *pT, *pW, *pG;
            if (cudaGetSymbolAddress(&pA, g_PhiA) == cudaSuccess &&
                cudaGetSymbolAddress(&pT, g_PhiT) == cudaSuccess &&
                cudaGetSymbolAddress(&pW, g_WT)  == cudaSuccess &&
                cudaGetSymbolAddress(&pG, g_GT)  == cudaSuccess) {
                use_tma = make_map(enc, &tA1, pA, DD, TT)    // Phi   [1920][4096]
                       && make_map(enc, &tB1, pW, DD, DD)    // WT    [4096][4096]
                       && make_map(enc, &tA2, pT, TT, DD)    // PhiT  [4096][1920]
                       && make_map(enc, &tB2, pG, TT, DD);   // GT    [4096][1920]
            }
        }
    }

    prep_kernel<<<PHI_BLOCKS + WT_BLOCKS, 256>>>(freqs, W);

    if (use_tma) {
        gemm_kernel<1,1><<<dim3(32, 15), 256, SMEM_DYN>>>(b, afreqs, nullptr, tA1, tB1);
        gemm_kernel<2,1><<<dim3(32, 32), 256, SMEM_DYN>>>(nullptr, nullptr, Out, tA2, tB2);
    } else {
        gemm_kernel<1,0><<<dim3(32, 15), 256, SMEM_DYN>>>(b, afreqs, nullptr, tA1, tB1);
        gemm_kernel<2,0><<<dim3(32, 32), 256, SMEM_DYN>>>(nullptr, nullptr, Out, tA2, tB2);
    }
}